// round 1
// baseline (speedup 1.0000x reference)
#include <cuda_runtime.h>
#include <math.h>

// Scratch: one full-size intermediate buffer (B*M*N floats = 134 MB).
// __device__ global (static allocation at module load) per the harness rules.
#define SCRATCH_ELEMS (2ull * 4096ull * 4096ull)
__device__ float g_scratch[SCRATCH_ELEMS];

__device__ __forceinline__ float2 cmulf(float2 a, float2 b) {
    return make_float2(a.x * b.x - a.y * b.y, a.x * b.y + a.y * b.x);
}

// ---------------------------------------------------------------------------
// Fused Makhoul pre-twiddle + 4096-pt inverse complex FFT (unnormalized,
// e^{+2*pi*i*nk/N}) + de-interleave epilogue, one CTA per row.
//
// MODE 0: IDCT-II inverse:  V_k = 0.5*(X_k - i*X_{n-k}) * expk_k   (X_{n-0}=0)
//         y_{2m} = v_m ; y_{2m+1} = v_{n-1-m}
// MODE 1: IDXST:            V_k = 0.5*(X_{n-k} - i*X_k) * expk_k   (k=0 -> 0)
//         y_{2m} = v_m ; y_{2m+1} = -v_{n-1-m}
//
// FFT: radix-4 Stockham (DIF, autosort), 6 stages for n=4096, ping-pong
// buffers in shared memory. Twiddles computed on the fly with sincosf.
// ---------------------------------------------------------------------------
template <int MODE>
__global__ __launch_bounds__(512)
void dct_fft_kernel(const float* __restrict__ in,
                    const float2* __restrict__ expk,
                    float* __restrict__ out, int n) {
    extern __shared__ float smf[];
    float*  xs   = smf;                       // n floats (input row)
    float2* bufA = (float2*)(smf + n);        // n complex
    float2* bufB = bufA + n;                  // n complex

    const int tid = threadIdx.x;
    const int T   = blockDim.x;
    const size_t base = (size_t)blockIdx.x * (size_t)n;

    // Load input row (coalesced).
    for (int i = tid; i < n; i += T) xs[i] = in[base + i];
    __syncthreads();

    // Build half-spectrum V with twiddle expk.
    for (int k = tid; k < n; k += T) {
        float Xa, Xb;
        if (MODE == 0) {
            Xa = xs[k];
            Xb = (k == 0) ? 0.0f : xs[n - k];
        } else {
            Xa = (k == 0) ? 0.0f : xs[n - k];
            Xb = (k == 0) ? 0.0f : xs[k];
        }
        float2 e = expk[k];
        // 0.5 * (Xa - i*Xb) * (e.x + i*e.y)
        bufA[k] = make_float2(0.5f * (Xa * e.x + Xb * e.y),
                              0.5f * (Xa * e.y - Xb * e.x));
    }

    // Radix-4 Stockham inverse FFT (unnormalized).
    float2* src = bufA;
    float2* dst = bufB;
    const int quarter = n >> 2;
    int m = quarter;  // quarter-length of current sub-transform
    int s = 1;        // stride (number of interleaved sub-sequences)
    while (m >= 1) {
        __syncthreads();
        const float astep = (float)(M_PI / (2.0 * (double)m));  // 2*pi/(4m)
        for (int idx = tid; idx < quarter; idx += T) {
            const int p = idx / s;
            const int q = idx - p * s;
            float2 a = src[idx];
            float2 b = src[idx + quarter];
            float2 c = src[idx + 2 * quarter];
            float2 d = src[idx + 3 * quarter];

            float s1, c1;
            sincosf(astep * (float)p, &s1, &c1);
            const float2 w1 = make_float2(c1, s1);
            const float2 w2 = cmulf(w1, w1);
            const float2 w3 = cmulf(w2, w1);

            // 4-point inverse DFT across quarters (B_r = a + i^r b + i^2r c + i^3r d)
            const float2 e0 = make_float2(a.x + c.x, a.y + c.y);
            const float2 e1 = make_float2(a.x - c.x, a.y - c.y);
            const float2 o0 = make_float2(b.x + d.x, b.y + d.y);
            const float2 o1 = make_float2(b.x - d.x, b.y - d.y);
            const float2 B0 = make_float2(e0.x + o0.x, e0.y + o0.y);
            const float2 B2 = make_float2(e0.x - o0.x, e0.y - o0.y);
            const float2 B1 = make_float2(e1.x - o1.y, e1.y + o1.x);  // e1 + i*o1
            const float2 B3 = make_float2(e1.x + o1.y, e1.y - o1.x);  // e1 - i*o1

            const int ob = q + 4 * s * p;
            dst[ob]         = B0;
            dst[ob + s]     = cmulf(B1, w1);
            dst[ob + 2 * s] = cmulf(B2, w2);
            dst[ob + 3 * s] = cmulf(B3, w3);
        }
        float2* t = src; src = dst; dst = t;
        s <<= 2;
        m >>= 2;
    }
    __syncthreads();

    // Epilogue: take real part, de-interleave, (optional) alternate sign.
    float2* outv = (float2*)(out + base);
    const int h = n >> 1;
    for (int i = tid; i < h; i += T) {
        const float v0 = src[i].x;
        const float v1 = src[n - 1 - i].x;
        outv[i] = (MODE == 0) ? make_float2(v0, v1) : make_float2(v0, -v1);
    }
}

// ---------------------------------------------------------------------------
// Batched 2D transpose: (B, R, C) -> (B, C, R). 32x32 tiles, 32x8 threads.
// ---------------------------------------------------------------------------
__global__ __launch_bounds__(256)
void transpose_kernel(const float* __restrict__ in, float* __restrict__ out,
                      int R, int C) {
    __shared__ float tile[32][33];
    const size_t off = (size_t)blockIdx.z * (size_t)R * (size_t)C;
    const int c0 = blockIdx.x * 32;
    const int r0 = blockIdx.y * 32;
#pragma unroll
    for (int i = threadIdx.y; i < 32; i += 8) {
        tile[i][threadIdx.x] =
            in[off + (size_t)(r0 + i) * C + (c0 + threadIdx.x)];
    }
    __syncthreads();
#pragma unroll
    for (int i = threadIdx.y; i < 32; i += 8) {
        out[off + (size_t)(c0 + i) * R + (r0 + threadIdx.x)] =
            tile[threadIdx.x][i];
    }
}

extern "C" void kernel_launch(void* const* d_in, const int* in_sizes, int n_in,
                              void* d_out, int out_size) {
    const float*  x     = (const float*)d_in[0];
    const float2* expkM = (const float2*)d_in[1];
    const float2* expkN = (const float2*)d_in[2];
    const int M = in_sizes[1] / 2;
    const int N = in_sizes[2] / 2;
    const int B = in_sizes[0] / (M * N);
    float* out = (float*)d_out;

    float* scratch = nullptr;
    cudaGetSymbolAddress((void**)&scratch, g_scratch);

    const int smemN = N * 4 + N * 16;  // xs + two complex ping-pong buffers
    const int smemM = M * 4 + M * 16;
    cudaFuncSetAttribute(dct_fft_kernel<1>,
                         cudaFuncAttributeMaxDynamicSharedMemorySize, smemN);
    cudaFuncSetAttribute(dct_fft_kernel<0>,
                         cudaFuncAttributeMaxDynamicSharedMemorySize, smemM);

    // Pass 1: IDXST along N (contiguous).  x -> scratch   (B, M, N)
    dct_fft_kernel<1><<<B * M, 512, smemN>>>(x, expkN, scratch, N);

    // Pass 2: transpose (B, M, N) -> (B, N, M).  scratch -> d_out
    {
        dim3 grid(N / 32, M / 32, B), blk(32, 8);
        transpose_kernel<<<grid, blk>>>(scratch, out, M, N);
    }

    // Pass 3: IDCT along M (contiguous in transposed layout).  d_out -> scratch
    dct_fft_kernel<0><<<B * N, 512, smemM>>>(out, expkM, scratch, M);

    // Pass 4: transpose (B, N, M) -> (B, M, N).  scratch -> d_out
    {
        dim3 grid(M / 32, N / 32, B), blk(32, 8);
        transpose_kernel<<<grid, blk>>>(scratch, out, N, M);
    }
}

// round 2
// speedup vs baseline: 4.4804x; 4.4804x over previous
#include <cuda_runtime.h>
#include <math.h>

// Scratch: one full-size intermediate buffer (B*M*N floats = 134 MB).
#define SCRATCH_ELEMS (2ull * 4096ull * 4096ull)
__device__ float g_scratch[SCRATCH_ELEMS];

// Problem shape is fixed: B=2, M=N=4096. FFT length h = 2048.
#define NN   4096
#define HH   2048

__device__ __forceinline__ float2 cadd(float2 a, float2 b){ return make_float2(a.x+b.x, a.y+b.y); }
__device__ __forceinline__ float2 csub(float2 a, float2 b){ return make_float2(a.x-b.x, a.y-b.y); }
__device__ __forceinline__ float2 cmul(float2 a, float2 b){
    return make_float2(fmaf(a.x, b.x, -a.y*b.y), fmaf(a.x, b.y, a.y*b.x));
}
__device__ __forceinline__ float2 mulip(float2 a){ return make_float2(-a.y, a.x); }  // a * (+i)

// Padded shared index: insert one float2 of pad every 8 float2 (kills the
// 16-word-stride store conflicts of the Stockham scatter).
#define PIDX(a) ((a) + ((a) >> 3))
#define PBUF    (HH + (HH >> 3))   // 2304 float2 per buffer

// Radix-8 Stockham stage (inverse FFT, e^{+2pi i}), 2048 points, 256 threads,
// one butterfly per thread. S = stride (1, 8, 64). eighth = 256.
template <int S>
__device__ __forceinline__ void r8_stage(const float2* __restrict__ src,
                                         float2* __restrict__ dst, int tid) {
    const int idx = tid;
    const int p = idx / S;          // compile-time S -> shift
    const int j = idx - p * S;

    float2 a[8];
#pragma unroll
    for (int t = 0; t < 8; t++) a[t] = src[PIDX(idx + 256 * t)];

    float2 e0 = cadd(a[0], a[4]), e1 = cadd(a[1], a[5]);
    float2 e2 = cadd(a[2], a[6]), e3 = cadd(a[3], a[7]);
    float2 o0 = csub(a[0], a[4]), o1 = csub(a[1], a[5]);
    float2 o2 = csub(a[2], a[6]), o3 = csub(a[3], a[7]);

    const float C8 = 0.70710678118654752f;
    o1 = make_float2(C8 * (o1.x - o1.y), C8 * (o1.x + o1.y));   // * e^{i pi/4}
    o2 = mulip(o2);                                              // * i
    o3 = make_float2(-C8 * (o3.x + o3.y), C8 * (o3.x - o3.y));   // * e^{3i pi/4}

    // even 4-pt inverse DFT -> B0,B2,B4,B6
    float2 t0 = cadd(e0, e2), t1 = csub(e0, e2);
    float2 t2 = cadd(e1, e3), t3 = csub(e1, e3);
    float2 it3 = mulip(t3);
    float2 B0 = cadd(t0, t2), B4 = csub(t0, t2);
    float2 B2 = cadd(t1, it3), B6 = csub(t1, it3);
    // odd 4-pt inverse DFT -> B1,B3,B5,B7
    float2 u0 = cadd(o0, o2), u1 = csub(o0, o2);
    float2 u2 = cadd(o1, o3), u3 = csub(o1, o3);
    float2 iu3 = mulip(u3);
    float2 B1 = cadd(u0, u2), B5 = csub(u0, u2);
    float2 B3 = cadd(u1, iu3), B7 = csub(u1, iu3);

    // Twiddles: W = e^{2pi i * p * S / 2048}, outputs scaled by W^u.
    const float ANG = (float)(2.0 * M_PI * (double)S / 2048.0);
    float sn, cs;
    __sincosf(ANG * (float)p, &sn, &cs);
    const float2 w1 = make_float2(cs, sn);
    const float2 w2 = cmul(w1, w1);
    const float2 w3 = cmul(w2, w1);
    const float2 w4 = cmul(w2, w2);
    const float2 w5 = cmul(w4, w1);
    const float2 w6 = cmul(w3, w3);
    const float2 w7 = cmul(w4, w3);

    const int ob = j + 8 * S * p;
    dst[PIDX(ob)]         = B0;
    dst[PIDX(ob + S)]     = cmul(B1, w1);
    dst[PIDX(ob + 2 * S)] = cmul(B2, w2);
    dst[PIDX(ob + 3 * S)] = cmul(B3, w3);
    dst[PIDX(ob + 4 * S)] = cmul(B4, w4);
    dst[PIDX(ob + 5 * S)] = cmul(B5, w5);
    dst[PIDX(ob + 6 * S)] = cmul(B6, w6);
    dst[PIDX(ob + 7 * S)] = cmul(B7, w7);
}

// ---------------------------------------------------------------------------
// Fused: Makhoul pre-twiddle -> real-packed G (length 2048) -> 2048-pt inverse
// complex FFT (radix 8,8,8,4 Stockham) -> de-interleave epilogue.
// MODE 0 = IDCT-II inverse, MODE 1 = IDXST. One CTA (256 threads) per row.
// ---------------------------------------------------------------------------
template <int MODE>
__global__ __launch_bounds__(256)
void dct_fft_kernel(const float* __restrict__ in,
                    const float2* __restrict__ expk,
                    float* __restrict__ out) {
    __shared__ __align__(16) float2 sA[PBUF];
    __shared__ __align__(16) float2 sB[PBUF];
    float* xs = (float*)sB;   // input row aliases sB (dead after prologue)

    const int tid = threadIdx.x;
    const size_t base = (size_t)blockIdx.x * (size_t)NN;

    // Load input row (float4-coalesced).
    {
        const float4* in4 = (const float4*)(in + base);
        float4* xs4 = (float4*)xs;
#pragma unroll
        for (int i = tid; i < NN / 4; i += 256) xs4[i] = in4[i];
    }
    __syncthreads();

    // Prologue: V_k = 0.5*(Xa - i*Xb)*expk_k ; pack Hermitian V into
    // G_j = (V_j + V_{j+h}) + i * e^{2pi i j/n} * (V_j - V_{j+h}).
    {
        const float WANG = (float)(2.0 * M_PI / (double)NN);
#pragma unroll
        for (int j = tid; j < HH; j += 256) {
            float Xa0, Xb0, Xa1, Xb1;
            if (MODE == 0) {
                Xa0 = xs[j];            Xb0 = (j == 0) ? 0.0f : xs[NN - j];
                Xa1 = xs[j + HH];       Xb1 = xs[HH - j + ((j == 0) ? -HH + HH : 0)];
                Xb1 = xs[(j == 0) ? HH : (HH - j)];
            } else {
                Xa0 = (j == 0) ? 0.0f : xs[NN - j];
                Xb0 = (j == 0) ? 0.0f : xs[j];
                Xa1 = xs[(j == 0) ? HH : (HH - j)];
                Xb1 = xs[j + HH];
            }
            float2 ea = expk[j];
            float2 eb = expk[j + HH];
            float2 V0 = make_float2(0.5f * (Xa0 * ea.x + Xb0 * ea.y),
                                    0.5f * (Xa0 * ea.y - Xb0 * ea.x));
            float2 V1 = make_float2(0.5f * (Xa1 * eb.x + Xb1 * eb.y),
                                    0.5f * (Xa1 * eb.y - Xb1 * eb.x));
            float2 S = cadd(V0, V1);
            float2 D = csub(V0, V1);
            float sn, cs;
            __sincosf(WANG * (float)j, &sn, &cs);
            float2 wd = cmul(make_float2(cs, sn), D);
            sA[PIDX(j)] = make_float2(S.x - wd.y, S.y + wd.x);  // S + i*wd
        }
    }
    __syncthreads();

    // 2048-pt inverse FFT: radix 8 (s=1), 8 (s=8), 8 (s=64), 4 (s=512).
    r8_stage<1>(sA, sB, tid);  __syncthreads();
    r8_stage<8>(sB, sA, tid);  __syncthreads();
    r8_stage<64>(sA, sB, tid); __syncthreads();
    {   // final radix-4, s=512, no twiddles (p==0); 2 butterflies/thread
#pragma unroll
        for (int idx = tid; idx < 512; idx += 256) {
            float2 a0 = sB[PIDX(idx)],        a1 = sB[PIDX(idx + 512)];
            float2 a2 = sB[PIDX(idx + 1024)], a3 = sB[PIDX(idx + 1536)];
            float2 t0 = cadd(a0, a2), t1 = csub(a0, a2);
            float2 t2 = cadd(a1, a3), t3 = csub(a1, a3);
            float2 it3 = mulip(t3);
            sA[PIDX(idx)]        = cadd(t0, t2);
            sA[PIDX(idx + 512)]  = cadd(t1, it3);
            sA[PIDX(idx + 1024)] = csub(t0, t2);
            sA[PIDX(idx + 1536)] = csub(t1, it3);
        }
    }
    __syncthreads();

    // Epilogue: z_m = v_{2m} + i v_{2m+1};  y[2m] = v_m, y[2m+1] = sgn*v_{n-1-m}.
    {
        float2* outv = (float2*)(out + base);
#pragma unroll
        for (int m = tid; m < HH; m += 256) {
            const int mh = m >> 1;
            const float2 z1 = sA[PIDX(mh)];
            const float2 z2 = sA[PIDX(2047 - mh)];
            float v0, v1;
            if (m & 1) { v0 = z1.y; v1 = z2.x; }
            else       { v0 = z1.x; v1 = z2.y; }
            outv[m] = make_float2(v0, (MODE == 1) ? -v1 : v1);
        }
    }
}

// ---------------------------------------------------------------------------
// Batched transpose (B, R, C) -> (B, C, R): 64x64 tiles, 256 threads,
// float4 global loads AND stores.
// ---------------------------------------------------------------------------
__global__ __launch_bounds__(256)
void transpose_kernel(const float* __restrict__ in, float* __restrict__ out,
                      int R, int C) {
    __shared__ float tile[64][65];
    const int tx = threadIdx.x & 15;          // 16 float4 columns
    const int ty = threadIdx.x >> 4;          // 16 rows per step
    const size_t off = (size_t)blockIdx.z * (size_t)R * (size_t)C;
    const int c0 = blockIdx.x * 64;
    const int r0 = blockIdx.y * 64;

#pragma unroll
    for (int k = 0; k < 4; k++) {
        const int r = ty + 16 * k;
        const float4 v = *(const float4*)(in + off + (size_t)(r0 + r) * C + (c0 + 4 * tx));
        tile[r][4 * tx + 0] = v.x;
        tile[r][4 * tx + 1] = v.y;
        tile[r][4 * tx + 2] = v.z;
        tile[r][4 * tx + 3] = v.w;
    }
    __syncthreads();
#pragma unroll
    for (int k = 0; k < 4; k++) {
        const int r = ty + 16 * k;            // output row within tile
        float4 v;
        v.x = tile[4 * tx + 0][r];
        v.y = tile[4 * tx + 1][r];
        v.z = tile[4 * tx + 2][r];
        v.w = tile[4 * tx + 3][r];
        *(float4*)(out + off + (size_t)(c0 + r) * R + (r0 + 4 * tx)) = v;
    }
}

extern "C" void kernel_launch(void* const* d_in, const int* in_sizes, int n_in,
                              void* d_out, int out_size) {
    const float*  x     = (const float*)d_in[0];
    const float2* expkM = (const float2*)d_in[1];
    const float2* expkN = (const float2*)d_in[2];
    const int M = in_sizes[1] / 2;            // 4096
    const int N = in_sizes[2] / 2;            // 4096
    const int B = in_sizes[0] / (M * N);      // 2
    float* out = (float*)d_out;

    float* scratch = nullptr;
    cudaGetSymbolAddress((void**)&scratch, g_scratch);

    // Pass 1: IDXST along N (contiguous rows).  x -> scratch   (B, M, N)
    dct_fft_kernel<1><<<B * M, 256>>>(x, expkN, scratch);

    // Pass 2: transpose (B, M, N) -> (B, N, M).  scratch -> d_out
    {
        dim3 grid(N / 64, M / 64, B), blk(256);
        transpose_kernel<<<grid, blk>>>(scratch, out, M, N);
    }

    // Pass 3: IDCT along M (contiguous in transposed layout).  d_out -> scratch
    dct_fft_kernel<0><<<B * N, 256>>>(out, expkM, scratch);

    // Pass 4: transpose (B, N, M) -> (B, M, N).  scratch -> d_out
    {
        dim3 grid(M / 64, N / 64, B), blk(256);
        transpose_kernel<<<grid, blk>>>(scratch, out, N, M);
    }
}

// round 3
// speedup vs baseline: 6.2040x; 1.3847x over previous
#include <cuda_runtime.h>
#include <math.h>

// Scratch: one full-size intermediate buffer (B*M*N floats = 134 MB).
#define SCRATCH_ELEMS (2ull * 4096ull * 4096ull)
__device__ float g_scratch[SCRATCH_ELEMS];

// Problem shape fixed: B=2, M=N=4096. Real-packed FFT length = 2048.
#define NN 4096
#define HH 2048

__device__ __forceinline__ float2 cadd(float2 a, float2 b){ return make_float2(a.x+b.x, a.y+b.y); }
__device__ __forceinline__ float2 csub(float2 a, float2 b){ return make_float2(a.x-b.x, a.y-b.y); }
__device__ __forceinline__ float2 cmul(float2 a, float2 b){
    return make_float2(fmaf(a.x, b.x, -a.y*b.y), fmaf(a.x, b.y, a.y*b.x));
}
__device__ __forceinline__ float2 mulip(float2 a){ return make_float2(-a.y, a.x); }  // * (+i)

// Pad one float2 every 16: keeps every exchange phase conflict-free.
#define PIDX(a) ((a) + ((a) >> 4))
#define PBUF (HH + (HH >> 4))   // 2176 float2 = 17408 B

// ---- 16-point inverse DFT in registers (B_u = sum_t g_t e^{+2pi i t u/16}) ----
__device__ __forceinline__ void r16_bfly(float2 g[16]) {
    const float C8 = 0.70710678118654752f;
    const float2 W1 = make_float2( 0.92387953251128674f,  0.38268343236508978f);
    const float2 W2 = make_float2( C8,  C8);
    const float2 W3 = make_float2( 0.38268343236508978f,  0.92387953251128674f);
    const float2 W6 = make_float2(-C8,  C8);
    const float2 W9 = make_float2(-0.92387953251128674f, -0.38268343236508978f);

    float2 c[16];
#pragma unroll
    for (int t0 = 0; t0 < 4; t0++) {
        float2 x0 = g[t0], x1 = g[t0+4], x2 = g[t0+8], x3 = g[t0+12];
        float2 s02 = cadd(x0,x2), d02 = csub(x0,x2);
        float2 s13 = cadd(x1,x3), d13 = csub(x1,x3);
        float2 id13 = mulip(d13);
        c[t0*4+0] = cadd(s02,s13);
        c[t0*4+1] = cadd(d02,id13);
        c[t0*4+2] = csub(s02,s13);
        c[t0*4+3] = csub(d02,id13);
    }
    c[5]  = cmul(c[5],  W1);
    c[6]  = cmul(c[6],  W2);
    c[7]  = cmul(c[7],  W3);
    c[9]  = cmul(c[9],  W2);
    c[10] = mulip(c[10]);           // W16^4 = i
    c[11] = cmul(c[11], W6);
    c[13] = cmul(c[13], W3);
    c[14] = cmul(c[14], W6);
    c[15] = cmul(c[15], W9);
#pragma unroll
    for (int u0 = 0; u0 < 4; u0++) {
        float2 x0 = c[u0], x1 = c[4+u0], x2 = c[8+u0], x3 = c[12+u0];
        float2 s02 = cadd(x0,x2), d02 = csub(x0,x2);
        float2 s13 = cadd(x1,x3), d13 = csub(x1,x3);
        float2 id13 = mulip(d13);
        g[u0]    = cadd(s02,s13);
        g[u0+4]  = cadd(d02,id13);
        g[u0+8]  = csub(s02,s13);
        g[u0+12] = csub(d02,id13);
    }
}

// ---- 8-point inverse DFT in registers (no twiddles) ----
__device__ __forceinline__ void r8_bfly(float2 a[8]) {
    const float C8 = 0.70710678118654752f;
    float2 e0 = cadd(a[0],a[4]), e1 = cadd(a[1],a[5]);
    float2 e2 = cadd(a[2],a[6]), e3 = cadd(a[3],a[7]);
    float2 o0 = csub(a[0],a[4]), o1 = csub(a[1],a[5]);
    float2 o2 = csub(a[2],a[6]), o3 = csub(a[3],a[7]);
    o1 = make_float2(C8*(o1.x - o1.y),  C8*(o1.x + o1.y));   // * e^{i pi/4}
    o2 = mulip(o2);                                           // * i
    o3 = make_float2(-C8*(o3.x + o3.y), C8*(o3.x - o3.y));    // * e^{3i pi/4}
    float2 t0 = cadd(e0,e2), t1 = csub(e0,e2);
    float2 t2 = cadd(e1,e3), t3 = csub(e1,e3);
    float2 it3 = mulip(t3);
    float2 u0 = cadd(o0,o2), u1 = csub(o0,o2);
    float2 u2 = cadd(o1,o3), u3 = csub(o1,o3);
    float2 iu3 = mulip(u3);
    a[0] = cadd(t0,t2);  a[4] = csub(t0,t2);
    a[2] = cadd(t1,it3); a[6] = csub(t1,it3);
    a[1] = cadd(u0,u2);  a[5] = csub(u0,u2);
    a[3] = cadd(u1,iu3); a[7] = csub(u1,iu3);
}

// ---------------------------------------------------------------------------
// Fused: Makhoul pre-twiddle -> real-packed G (2048) -> radix 16/16/8 Stockham
// inverse FFT -> de-interleave epilogue. 128 threads, 16 complex per thread.
// MODE 0 = IDCT-II inverse, MODE 1 = IDXST. One CTA per row. 3 syncthreads.
// ---------------------------------------------------------------------------
template <int MODE>
__global__ __launch_bounds__(128, 4)
void dct_fft_kernel(const float* __restrict__ in,
                    const float2* __restrict__ expk,
                    float* __restrict__ out) {
    __shared__ __align__(16) float2 sX[PBUF];   // aliases the input row
    __shared__ __align__(16) float2 sY[PBUF];
    float* xs = (float*)sX;

    const int idx = threadIdx.x;   // 0..127
    const size_t base = (size_t)blockIdx.x * (size_t)NN;

    // Load input row (float4-coalesced) into xs (= sX storage).
    {
        const float4* in4 = (const float4*)(in + base);
        float4* xs4 = (float4*)xs;
#pragma unroll
        for (int i = idx; i < NN/4; i += 128) xs4[i] = in4[i];
    }
    __syncthreads();

    // ---- Stage A: prologue (G into registers) + radix-16 + twiddle, write sY.
    {
        float2 g[16];
        // w = e^{2pi i j/4096} at j = idx, stepped by E32 = e^{2pi i/32}.
        const float2 E32 = make_float2(0.98078528040323044f, 0.19509032201612827f);
        float sn, cs;
        __sincosf((float)(2.0*M_PI/4096.0) * (float)idx, &sn, &cs);
        float2 w = make_float2(cs, sn);
#pragma unroll
        for (int t = 0; t < 16; t++) {
            const int j = idx + 128*t;
            float Xa0, Xb0, Xa1, Xb1;
            if (MODE == 0) {
                Xa0 = xs[j];
                Xb0 = (j == 0) ? 0.0f : xs[NN - j];
                Xa1 = xs[j + HH];
                Xb1 = xs[(j == 0) ? HH : (HH - j)];
            } else {
                Xa0 = (j == 0) ? 0.0f : xs[NN - j];
                Xb0 = (j == 0) ? 0.0f : xs[j];
                Xa1 = xs[(j == 0) ? HH : (HH - j)];
                Xb1 = xs[j + HH];
            }
            const float2 ea = expk[j];
            const float2 eb = expk[j + HH];
            float2 V0 = make_float2(0.5f*(Xa0*ea.x + Xb0*ea.y),
                                    0.5f*(Xa0*ea.y - Xb0*ea.x));
            float2 V1 = make_float2(0.5f*(Xa1*eb.x + Xb1*eb.y),
                                    0.5f*(Xa1*eb.y - Xb1*eb.x));
            float2 S = cadd(V0, V1);
            float2 D = csub(V0, V1);
            float2 wd = cmul(w, D);
            g[t] = make_float2(S.x - wd.y, S.y + wd.x);   // S + i*wd
            w = cmul(w, E32);
        }
        r16_bfly(g);
        // stage twiddle W = e^{2pi i idx/2048}; outputs at 16*idx + u.
        __sincosf((float)(2.0*M_PI/2048.0) * (float)idx, &sn, &cs);
        const float2 w1 = make_float2(cs, sn);
        sY[PIDX(16*idx)] = g[0];
        float2 wu = w1;
#pragma unroll
        for (int u = 1; u < 16; u++) {
            sY[PIDX(16*idx + u)] = cmul(g[u], wu);
            wu = cmul(wu, w1);
        }
    }
    __syncthreads();

    // ---- Stage B: radix-16, S=16. Read sY, write sX (xs is dead).
    {
        float2 g[16];
#pragma unroll
        for (int t = 0; t < 16; t++) g[t] = sY[PIDX(idx + 128*t)];
        r16_bfly(g);
        const int p = idx >> 4, j = idx & 15;
        float sn, cs;
        __sincosf((float)(2.0*M_PI/128.0) * (float)p, &sn, &cs);
        const float2 w1 = make_float2(cs, sn);
        const int ob = j + 256*p;
        sX[PIDX(ob)] = g[0];
        float2 wu = w1;
#pragma unroll
        for (int u = 1; u < 16; u++) {
            sX[PIDX(ob + 16*u)] = cmul(g[u], wu);
            wu = cmul(wu, w1);
        }
    }
    __syncthreads();

    // ---- Stage C: radix-8, S=256 (twiddle-free) fused with epilogue.
    // Thread handles butterflies b1 = idx and b2 = 255-idx, yielding the
    // conjugate-position pairs (mh, 2047-mh) entirely in registers.
    {
        const int b1 = idx, b2 = 255 - idx;
        float2 A[8], Bv[8];
#pragma unroll
        for (int u = 0; u < 8; u++) A[u]  = sX[PIDX(b1 + 256*u)];
#pragma unroll
        for (int u = 0; u < 8; u++) Bv[u] = sX[PIDX(b2 + 256*u)];
        r8_bfly(A);   // z[b1 + 256u]
        r8_bfly(Bv);  // z[b2 + 256u]

        const float sgn = (MODE == 1) ? -1.0f : 1.0f;
        float4* out4 = (float4*)(out + base);   // 1024 float4 per row
#pragma unroll
        for (int u = 0; u < 4; u++) {
            // mh = b1 + 256u  (< 1024); partner z[2047-mh] = Bv[7-u]
            float2 z1 = A[u], z2 = Bv[7-u];
            out4[b1 + 256*u] = make_float4(z1.x, sgn*z2.y, z1.y, sgn*z2.x);
            // mh = b2 + 256u  (< 1024); partner z[2047-mh] = A[7-u]
            z1 = Bv[u]; z2 = A[7-u];
            out4[b2 + 256*u] = make_float4(z1.x, sgn*z2.y, z1.y, sgn*z2.x);
        }
    }
}

// ---------------------------------------------------------------------------
// Batched transpose (B, R, C) -> (B, C, R): 64x64 tiles, 256 threads,
// float4 global loads AND stores.
// ---------------------------------------------------------------------------
__global__ __launch_bounds__(256)
void transpose_kernel(const float* __restrict__ in, float* __restrict__ out,
                      int R, int C) {
    __shared__ float tile[64][65];
    const int tx = threadIdx.x & 15;
    const int ty = threadIdx.x >> 4;
    const size_t off = (size_t)blockIdx.z * (size_t)R * (size_t)C;
    const int c0 = blockIdx.x * 64;
    const int r0 = blockIdx.y * 64;

#pragma unroll
    for (int k = 0; k < 4; k++) {
        const int r = ty + 16*k;
        const float4 v = *(const float4*)(in + off + (size_t)(r0 + r)*C + (c0 + 4*tx));
        tile[r][4*tx+0] = v.x;
        tile[r][4*tx+1] = v.y;
        tile[r][4*tx+2] = v.z;
        tile[r][4*tx+3] = v.w;
    }
    __syncthreads();
#pragma unroll
    for (int k = 0; k < 4; k++) {
        const int r = ty + 16*k;
        float4 v;
        v.x = tile[4*tx+0][r];
        v.y = tile[4*tx+1][r];
        v.z = tile[4*tx+2][r];
        v.w = tile[4*tx+3][r];
        *(float4*)(out + off + (size_t)(c0 + r)*R + (r0 + 4*tx)) = v;
    }
}

extern "C" void kernel_launch(void* const* d_in, const int* in_sizes, int n_in,
                              void* d_out, int out_size) {
    const float*  x     = (const float*)d_in[0];
    const float2* expkM = (const float2*)d_in[1];
    const float2* expkN = (const float2*)d_in[2];
    const int M = in_sizes[1] / 2;            // 4096
    const int N = in_sizes[2] / 2;            // 4096
    const int B = in_sizes[0] / (M * N);      // 2
    float* out = (float*)d_out;

    float* scratch = nullptr;
    cudaGetSymbolAddress((void**)&scratch, g_scratch);

    // Pass 1: IDXST along N (contiguous rows).  x -> scratch   (B, M, N)
    dct_fft_kernel<1><<<B * M, 128>>>(x, expkN, scratch);

    // Pass 2: transpose (B, M, N) -> (B, N, M).  scratch -> d_out
    {
        dim3 grid(N / 64, M / 64, B), blk(256);
        transpose_kernel<<<grid, blk>>>(scratch, out, M, N);
    }

    // Pass 3: IDCT along M (contiguous in transposed layout).  d_out -> scratch
    dct_fft_kernel<0><<<B * N, 128>>>(out, expkM, scratch);

    // Pass 4: transpose (B, N, M) -> (B, M, N).  scratch -> d_out
    {
        dim3 grid(M / 64, N / 64, B), blk(256);
        transpose_kernel<<<grid, blk>>>(scratch, out, N, M);
    }
}